// round 6
// baseline (speedup 1.0000x reference)
#include <cuda_runtime.h>

// ---------------------------------------------------------------------------
// Fused SAN (pairwise) block, fp32 + packed f32x2 FMA, sm_103a.
// Restructure: out = W3 * (sum_k softmax_k * x[neighbor_k]) + b3
//   -> phase-1 conv computes only x1,x2 (16 ch); aggregation acts on raw x;
//      final 64x64 GEMM runs on interior pixels only.
// ---------------------------------------------------------------------------

#define TILE_W 32
#define TILE_H 8
#define HW_    34
#define NHP    340        // halo pixels (34 x 10)
#define NTHREADS 512
#define IMG 256
#define PLANE (IMG*IMG)

// shared-memory float offsets (u64/vec regions 16B-aligned)
#define XS    0           // x halo tile      [64][340]
#define CO    21760       // x1,x2 outputs    [16][340]
#define L_    27200       // logits           [9][256]
#define GIX   29504       // gather offsets   int[340]
#define T1    29856       // folded bn1 shift [10]
#define WO    29872       // folded w_out     [8]
#define PW    29880       // convp_w          [4]
#define BO    29884       // b_out            [1]
#define BS12  29888       // conv1/2 bias     [16]
#define B3    29904       // conv3 bias       [64]
#define T2P   29968       // folded bn2 shift pairs  u64[4]
#define WMP   29976       // folded w_mid pairs      u64[10][4]
#define W12P  30080       // conv1/2 weights dup-pairs u64[64][16]
#define W3P   32128       // conv3 weights dup-pairs   u64[64][64]
#define ZS    40320       // aggregated input pairs    u64[64][128]
#define SMEM_FLOATS 56704
#define SMEM_BYTES  (SMEM_FLOATS * 4)   // 226,816 B

typedef unsigned long long u64;

__device__ __forceinline__ u64 pk2(float x, float y) {
    u64 r; asm("mov.b64 %0, {%1, %2};" : "=l"(r) : "f"(x), "f"(y)); return r;
}
__device__ __forceinline__ float2 up2(u64 v) {
    float2 f; asm("mov.b64 {%0, %1}, %2;" : "=f"(f.x), "=f"(f.y) : "l"(v)); return f;
}
__device__ __forceinline__ u64 ffma2(u64 a, u64 b, u64 c) {
    u64 d; asm("fma.rn.f32x2 %0, %1, %2, %3;" : "=l"(d) : "l"(a), "l"(b), "l"(c)); return d;
}

__device__ __forceinline__ int reflect(int i) {
    if (i < 0) return -i;
    if (i > IMG - 1) return 2 * (IMG - 1) - i;
    return i;
}

__global__ void __launch_bounds__(NTHREADS, 1)
san_fused_kernel(const float* __restrict__ x,
                 const float* __restrict__ c1w, const float* __restrict__ c1b,
                 const float* __restrict__ c2w, const float* __restrict__ c2b,
                 const float* __restrict__ c3w, const float* __restrict__ c3b,
                 const float* __restrict__ cpw,
                 const float* __restrict__ bn1g, const float* __restrict__ bn1b,
                 const float* __restrict__ bn1m, const float* __restrict__ bn1v,
                 const float* __restrict__ wmid,
                 const float* __restrict__ bn2g, const float* __restrict__ bn2b,
                 const float* __restrict__ bn2m, const float* __restrict__ bn2v,
                 const float* __restrict__ wout, const float* __restrict__ bout,
                 float* __restrict__ out)
{
    extern __shared__ float sm[];
    const int tid = threadIdx.x;
    const int tx0 = blockIdx.x * TILE_W;
    const int ty0 = blockIdx.y * TILE_H;
    const int nb  = blockIdx.z;

    // ================= parameter staging + gather table =================
    if (tid < NHP) {
        int hy = tid / 34, hx = tid - hy * 34;
        int gy = reflect(ty0 - 1 + hy);
        int gx = reflect(tx0 - 1 + hx);
        ((int*)sm)[GIX + tid] = gy * IMG + gx;
    }
    // conv1/2 weights, duplicated pairs: W12P[c][o]
    for (int i = tid; i < 64 * 16; i += NTHREADS) {
        int c = i >> 4, o = i & 15;
        float w = (o < 8) ? c1w[o * 64 + c] : c2w[(o - 8) * 64 + c];
        *(u64*)(sm + W12P + 2 * i) = pk2(w, w);
    }
    // conv3 weights, duplicated pairs: W3P[c][o]
    for (int i = tid; i < 64 * 64; i += NTHREADS) {
        int c = i >> 6, o = i & 63;
        float w = c3w[o * 64 + c];
        *(u64*)(sm + W3P + 2 * i) = pk2(w, w);
    }
    if (tid < 10) {
        float s1 = bn1g[tid] * rsqrtf(bn1v[tid] + 1e-5f);
        sm[T1 + tid] = (bn1b[tid] - bn1m[tid] * s1) / s1;
    }
    if (tid >= 32 && tid < 36) {            // T2P pairs (bn2 shift, folded)
        int op = tid - 32;
        float tv[2];
        #pragma unroll
        for (int j = 0; j < 2; j++) {
            int o = 2 * op + j;
            float s2 = bn2g[o] * rsqrtf(bn2v[o] + 1e-5f);
            tv[j] = (bn2b[o] - bn2m[o] * s2) / s2;
        }
        *(u64*)(sm + T2P + 2 * op) = pk2(tv[0], tv[1]);
    }
    if (tid >= 64 && tid < 72) {            // w_out folded with bn2 scale
        int o = tid - 64;
        float s2 = bn2g[o] * rsqrtf(bn2v[o] + 1e-5f);
        sm[WO + o] = wout[o] * s2;
    }
    if (tid >= 96 && tid < 136) {           // WMP[c][op]: w_mid*s1, o-pairs
        int i = tid - 96; int c = i >> 2, op = i & 3;
        float s1c = bn1g[c] * rsqrtf(bn1v[c] + 1e-5f);
        *(u64*)(sm + WMP + 2 * i) =
            pk2(wmid[(2 * op) * 10 + c] * s1c, wmid[(2 * op + 1) * 10 + c] * s1c);
    }
    if (tid >= 160 && tid < 164) sm[PW + tid - 160] = cpw[tid - 160];
    if (tid == 192) sm[BO] = bout[0];
    if (tid >= 224 && tid < 240) {
        int o = tid - 224;
        sm[BS12 + o] = (o < 8) ? c1b[o] : c2b[o - 8];
    }
    if (tid >= 256 && tid < 320) sm[B3 + tid - 256] = c3b[tid - 256];
    __syncthreads();

    // ================= stage x halo via gather table =================
    {
        const float* xb = x + (size_t)nb * 64 * PLANE;
        const int* gix = (const int*)sm + GIX;
        #pragma unroll 4
        for (int i = tid; i < 64 * NHP; i += NTHREADS) {
            int c = i / NHP;
            int pix = i - c * NHP;
            sm[XS + i] = xb[(size_t)c * PLANE + gix[pix]];
        }
    }
    __syncthreads();

    // ================= phase 1: 16-ch conv over halo (f32x2 pairs) =======
    {
        const int w = tid >> 5, lane = tid & 31;
        const int og = w & 1;               // 8-out-channel group
        const int pb = w >> 1;              // pair block
        const int o0 = og * 8;
        int p = pb * 22 + lane;
        if (p > 169) p = 169;

        u64 acc[8];
        #pragma unroll
        for (int o = 0; o < 8; o++) { float b = sm[BS12 + o0 + o]; acc[o] = pk2(b, b); }

        const float* xp = sm + XS + 2 * p;
        #pragma unroll 4
        for (int c = 0; c < 64; c++) {
            u64 X = *(const u64*)xp; xp += NHP;
            const u64* W = (const u64*)(sm + W12P + 2 * (c * 16 + o0));
            #pragma unroll
            for (int o = 0; o < 8; o++) acc[o] = ffma2(W[o], X, acc[o]);
        }
        #pragma unroll
        for (int o = 0; o < 8; o++)
            *(u64*)(sm + CO + (o0 + o) * NHP + 2 * p) = acc[o];
    }
    __syncthreads();

    // ================= phase 2a: attention MLP logits (tap-split) ========
    {
        const int pix = tid & 255;
        const int tg  = tid >> 8;           // 0: taps 0-4, 1: taps 5-8
        const int iy = pix >> 5, ix = pix & 31;
        const int gx = tx0 + ix, gy = ty0 + iy;
        const int hs = (iy + 1) * HW_ + ix + 1;
        const float STEP = 2.0f / 255.0f;
        const float pw00 = sm[PW], pw01 = sm[PW + 1], pw10 = sm[PW + 2], pw11 = sm[PW + 3];
        const float t18 = sm[T1 + 8], t19 = sm[T1 + 9];

        float x1t[8];
        #pragma unroll
        for (int c = 0; c < 8; c++) x1t[c] = sm[CO + c * NHP + hs] + sm[T1 + c];

        u64 t2p[4], wm8[4], wm9[4];
        #pragma unroll
        for (int op = 0; op < 4; op++) {
            t2p[op] = *(const u64*)(sm + T2P + 2 * op);
            wm8[op] = *(const u64*)(sm + WMP + 2 * (8 * 4 + op));
            wm9[op] = *(const u64*)(sm + WMP + 2 * (9 * 4 + op));
        }

        int kk[5], hn[5];
        u64 h1p[5][4];
        #pragma unroll
        for (int kt = 0; kt < 5; kt++) {
            int k = tg * 5 + kt; if (k > 8) k = 8;     // tg1 duplicates tap 8 (benign)
            kk[kt] = k;
            int dy = k / 3 - 1, dx = k - (k / 3) * 3 - 1;
            hn[kt] = hs + dy * HW_ + dx;
            float dlw = (float)(gx - reflect(gx + dx)) * STEP;
            float dlh = (float)(gy - reflect(gy + dy)) * STEP;
            float a8 = fmaxf(pw00 * dlw + pw01 * dlh + t18, 0.0f);
            float a9 = fmaxf(pw10 * dlw + pw11 * dlh + t19, 0.0f);
            u64 a8p = pk2(a8, a8), a9p = pk2(a9, a9);
            #pragma unroll
            for (int op = 0; op < 4; op++)
                h1p[kt][op] = ffma2(wm8[op], a8p, ffma2(wm9[op], a9p, t2p[op]));
        }
        #pragma unroll
        for (int c = 0; c < 8; c++) {
            u64 wmc[4];
            #pragma unroll
            for (int op = 0; op < 4; op++)
                wmc[op] = *(const u64*)(sm + WMP + 2 * (c * 4 + op));
            const float x1c = x1t[c];
            const float* x2p = sm + CO + (8 + c) * NHP;
            #pragma unroll
            for (int kt = 0; kt < 5; kt++) {
                float a = fmaxf(x1c - x2p[hn[kt]], 0.0f);
                u64 ap = pk2(a, a);
                #pragma unroll
                for (int op = 0; op < 4; op++)
                    h1p[kt][op] = ffma2(wmc[op], ap, h1p[kt][op]);
            }
        }
        float woR[8];
        #pragma unroll
        for (int o = 0; o < 8; o++) woR[o] = sm[WO + o];
        const float boR = sm[BO];
        #pragma unroll
        for (int kt = 0; kt < 5; kt++) {
            float l = boR;
            #pragma unroll
            for (int op = 0; op < 4; op++) {
                float2 h = up2(h1p[kt][op]);
                l = fmaf(woR[2 * op],     fmaxf(h.x, 0.0f), l);
                l = fmaf(woR[2 * op + 1], fmaxf(h.y, 0.0f), l);
            }
            sm[L_ + kk[kt] * 256 + pix] = l;
        }
    }
    __syncthreads();

    // ================= phase 2b: softmax + aggregate raw x -> z ==========
    {
        const int pr = tid & 127;           // pixel-pair index
        const int cg = tid >> 7;            // channel group (16 ch)
        const int pix0 = pr * 2;
        const int iy = pix0 >> 5, ix0 = pix0 & 31;

        float l0[9], l1[9];
        #pragma unroll
        for (int k = 0; k < 9; k++) {
            float2 lv = *(const float2*)(sm + L_ + k * 256 + pix0);
            l0[k] = lv.x; l1[k] = lv.y;
        }
        float m0 = l0[0], m1 = l1[0];
        #pragma unroll
        for (int k = 1; k < 9; k++) { m0 = fmaxf(m0, l0[k]); m1 = fmaxf(m1, l1[k]); }
        float e0[9], e1[9], s0 = 0.0f, s1 = 0.0f;
        #pragma unroll
        for (int k = 0; k < 9; k++) {
            e0[k] = __expf(l0[k] - m0); s0 += e0[k];
            e1[k] = __expf(l1[k] - m1); s1 += e1[k];
        }
        const float i0 = 1.0f / s0, i1 = 1.0f / s1;
        u64 E[9];
        #pragma unroll
        for (int k = 0; k < 9; k++) E[k] = pk2(e0[k] * i0, e1[k] * i1);

        const float* cp0 = sm + XS + (cg * 16) * NHP + iy * HW_ + ix0;
        #pragma unroll 4
        for (int c = 0; c < 16; c++) {
            const float* cp = cp0 + c * NHP;
            u64 acc = 0ull;
            #pragma unroll
            for (int dy = 0; dy < 3; dy++) {
                const float* rp = cp + dy * HW_;
                u64 p0 = *(const u64*)rp;
                u64 p2 = *(const u64*)(rp + 2);
                float2 f01 = up2(p0), f23 = up2(p2);
                u64 p1 = pk2(f01.y, f23.x);
                acc = ffma2(E[dy * 3 + 0], p0, acc);
                acc = ffma2(E[dy * 3 + 1], p1, acc);
                acc = ffma2(E[dy * 3 + 2], p2, acc);
            }
            *(u64*)(sm + ZS + 2 * ((cg * 16 + c) * 128 + pr)) = acc;
        }
    }
    __syncthreads();

    // ================= phase 3: out = W3 * z + b3 (64x64x256 GEMM) =======
    {
        const int w = tid >> 5, lane = tid & 31;
        const int ogc = w & 3;              // 16-out-channel group
        const int pb  = w >> 2;             // pair block of 32
        const int o0 = ogc * 16;
        const int p  = pb * 32 + lane;

        u64 acc[16];
        #pragma unroll
        for (int o = 0; o < 16; o++) { float b = sm[B3 + o0 + o]; acc[o] = pk2(b, b); }

        #pragma unroll 2
        for (int c = 0; c < 64; c++) {
            u64 Z = *(const u64*)(sm + ZS + 2 * (c * 128 + p));
            const u64* W = (const u64*)(sm + W3P + 2 * (c * 64 + o0));
            #pragma unroll
            for (int o = 0; o < 16; o++) acc[o] = ffma2(W[o], Z, acc[o]);
        }

        const int iy = p >> 4, ix0 = (p & 15) * 2;
        float* op = out + ((size_t)nb * 64 + o0) * PLANE + (ty0 + iy) * IMG + tx0 + ix0;
        #pragma unroll
        for (int o = 0; o < 16; o++)
            *(u64*)(op + (size_t)o * PLANE) = acc[o];
    }
}

extern "C" void kernel_launch(void* const* d_in, const int* in_sizes, int n_in,
                              void* d_out, int out_size)
{
    const float* x     = (const float*)d_in[0];
    const float* c1w   = (const float*)d_in[1];
    const float* c1b   = (const float*)d_in[2];
    const float* c2w   = (const float*)d_in[3];
    const float* c2b   = (const float*)d_in[4];
    const float* c3w   = (const float*)d_in[5];
    const float* c3b   = (const float*)d_in[6];
    const float* cpw   = (const float*)d_in[7];
    // d_in[8] = convp_b (cancels in position differences)
    const float* bn1g  = (const float*)d_in[9];
    const float* bn1b  = (const float*)d_in[10];
    const float* bn1m  = (const float*)d_in[11];
    const float* bn1v  = (const float*)d_in[12];
    const float* wmid  = (const float*)d_in[13];
    const float* bn2g  = (const float*)d_in[14];
    const float* bn2b  = (const float*)d_in[15];
    const float* bn2m  = (const float*)d_in[16];
    const float* bn2v  = (const float*)d_in[17];
    const float* wout  = (const float*)d_in[18];
    const float* bout  = (const float*)d_in[19];
    float* out = (float*)d_out;

    const int n = in_sizes[0] / (64 * PLANE);   // 16

    cudaFuncSetAttribute(san_fused_kernel,
                         cudaFuncAttributeMaxDynamicSharedMemorySize, SMEM_BYTES);

    dim3 grid(IMG / TILE_W, IMG / TILE_H, n);   // (8, 32, 16)
    san_fused_kernel<<<grid, NTHREADS, SMEM_BYTES>>>(
        x, c1w, c1b, c2w, c2b, c3w, c3b, cpw,
        bn1g, bn1b, bn1m, bn1v, wmid,
        bn2g, bn2b, bn2m, bn2v, wout, bout, out);
}

// round 7
// speedup vs baseline: 1.7047x; 1.7047x over previous
#include <cuda_runtime.h>

// ---------------------------------------------------------------------------
// Fused SAN (pairwise) block, fp32 + packed f32x2 FMA (FFMA2), sm_103a.
// R5 structure (80-ch conv over halo, MLP, softmax, aggregation of x3)
// + chunked staging/conv software pipeline (4 chunks of 16 channels).
// ---------------------------------------------------------------------------

#define TILE_W 32
#define TILE_H 8
#define HW_    34
#define NHP    340         // halo pixels (34*10)
#define NTHREADS 512
#define IMG 256
#define PLANE (IMG*IMG)

#define NCHUNK 4
#define CPC    16                  // channels per chunk
#define CHELEMS (CPC*NHP)          // 5440 floats per chunk
#define KMAX   11                  // ceil(5440/512)

// shared-memory float offsets
#define XS   0                       // x halo tile  [64][340]   (dead after phase1; aliased by L)
#define L_   0                       // logits       [9][256]    (alias of XS)
#define CO   21760                   // conv outputs [80][340]   (0..7 x1, 8..15 x2, 16..79 x3)
#define WTT  48960                   // weights      [8 og][64 c][12] (10 used + 2 pad)
#define BS   55104                   // conv biases  [80]
#define T1   55184                   // folded bn1 shift   [10]
#define T2   55194                   // folded bn2 shift   [8]
#define WM   55202                   // folded w_mid (pre-scaled by s1) [8][10]
#define WO   55282                   // folded w_out (pre-scaled by s2) [8]
#define PW   55290                   // convp_w [4]
#define BO   55294                   // b_out [1]
#define SMEM_FLOATS 55296
#define SMEM_BYTES  (SMEM_FLOATS * 4)

typedef unsigned long long u64;

__device__ __forceinline__ u64 pk2(float x, float y) {
    u64 r; asm("mov.b64 %0, {%1, %2};" : "=l"(r) : "f"(x), "f"(y)); return r;
}
__device__ __forceinline__ float2 up2(u64 v) {
    float2 f; asm("mov.b64 {%0, %1}, %2;" : "=f"(f.x), "=f"(f.y) : "l"(v)); return f;
}
__device__ __forceinline__ u64 ffma2(u64 a, u64 b, u64 c) {
    u64 d; asm("fma.rn.f32x2 %0, %1, %2, %3;" : "=l"(d) : "l"(a), "l"(b), "l"(c)); return d;
}

__device__ __forceinline__ int reflect(int i) {
    if (i < 0) return -i;
    if (i > IMG - 1) return 2 * (IMG - 1) - i;
    return i;
}

__global__ void __launch_bounds__(NTHREADS, 1)
san_fused_kernel(const float* __restrict__ x,
                 const float* __restrict__ c1w, const float* __restrict__ c1b,
                 const float* __restrict__ c2w, const float* __restrict__ c2b,
                 const float* __restrict__ c3w, const float* __restrict__ c3b,
                 const float* __restrict__ cpw,
                 const float* __restrict__ bn1g, const float* __restrict__ bn1b,
                 const float* __restrict__ bn1m, const float* __restrict__ bn1v,
                 const float* __restrict__ wmid,
                 const float* __restrict__ bn2g, const float* __restrict__ bn2b,
                 const float* __restrict__ bn2m, const float* __restrict__ bn2v,
                 const float* __restrict__ wout, const float* __restrict__ bout,
                 float* __restrict__ out)
{
    extern __shared__ float sm[];
    const int tid = threadIdx.x;
    const int tx0 = blockIdx.x * TILE_W;
    const int ty0 = blockIdx.y * TILE_H;
    const int nb  = blockIdx.z;

    // ---------------- parameter staging (no cross-thread deps) ----------------
    for (int i = tid; i < 8 * 64 * 12; i += NTHREADS) {
        int og = i / 768; int rem = i - og * 768;
        int c = rem / 12;  int j = rem - c * 12;
        float w = 0.0f;
        if (j < 10) {
            int o = og * 10 + j;
            w = (o < 8) ? c1w[o * 64 + c] : (o < 16) ? c2w[(o - 8) * 64 + c]
                                                     : c3w[(o - 16) * 64 + c];
        }
        sm[WTT + i] = w;
    }
    if (tid < 80)
        sm[BS + tid] = (tid < 8) ? c1b[tid] : (tid < 16) ? c2b[tid - 8] : c3b[tid - 16];
    if (tid >= 128 && tid < 208) {           // folded w_mid
        int i = tid - 128; int c = i % 10;
        float s1 = bn1g[c] * rsqrtf(bn1v[c] + 1e-5f);
        sm[WM + i] = wmid[i] * s1;
    }
    if (tid >= 224 && tid < 234) {           // folded bn1 shift
        int c = tid - 224;
        float s1 = bn1g[c] * rsqrtf(bn1v[c] + 1e-5f);
        sm[T1 + c] = (bn1b[c] - bn1m[c] * s1) / s1;
    }
    if (tid >= 256 && tid < 264) {           // folded bn2 / w_out
        int o = tid - 256;
        float s2 = bn2g[o] * rsqrtf(bn2v[o] + 1e-5f);
        sm[T2 + o] = (bn2b[o] - bn2m[o] * s2) / s2;
        sm[WO + o] = wout[o] * s2;
    }
    if (tid >= 288 && tid < 292) sm[PW + tid - 288] = cpw[tid - 288];
    if (tid == 320) sm[BO] = bout[0];

    // ---------------- staging prologue: per-thread gather offsets -------------
    const float* xb = x + (size_t)nb * 64 * PLANE;
    int goff[KMAX];                 // cl*PLANE + gy*IMG + gx  (chunk-local)
    #pragma unroll
    for (int k = 0; k < KMAX; k++) {
        int i = tid + k * NTHREADS;
        if (i >= CHELEMS) { goff[k] = -1; continue; }
        int cl  = i / NHP;
        int pix = i - cl * NHP;
        int hy  = pix / HW_;
        int hx  = pix - hy * HW_;
        int gy  = reflect(ty0 - 1 + hy);
        int gx  = reflect(tx0 - 1 + hx);
        goff[k] = cl * PLANE + gy * IMG + gx;
    }
    #pragma unroll
    for (int k = 0; k < KMAX; k++)
        if (goff[k] < 0) goff[k] = goff[0];   // replicate elem 0 (store lands in a
                                              // region rewritten before any read)
    float r[KMAX];
    #pragma unroll
    for (int k = 0; k < KMAX; k++) r[k] = xb[goff[k]];          // chunk 0 in flight

    // ---------------- phase 1: pipelined staging + 80-ch conv -----------------
    const int w    = tid >> 5;
    const int lane = tid & 31;
    const int og   = w & 7;           // out-channel group (10 ch)
    const int half = w >> 3;          // pixel-pair half
    const int o0   = og * 10;
    const int pbase = half * 88;
    const int lim   = half ? 170 : 88;

    int ppc[3];
    #pragma unroll
    for (int rr = 0; rr < 3; rr++) {
        int pp = pbase + rr * 32 + lane;
        ppc[rr] = (pp < lim) ? pp : (lim - 1);
    }

    u64 acc[3][10];
    const float* wrow = sm + WTT + og * 768;
    const float* xp0 = sm + XS + 2 * ppc[0];
    const float* xp1 = sm + XS + 2 * ppc[1];
    const float* xp2 = sm + XS + 2 * ppc[2];

    for (int ch = 0; ch < NCHUNK; ch++) {
        // store staged chunk
        float* dst = sm + XS + ch * CHELEMS + tid;
        #pragma unroll
        for (int k = 0; k < KMAX; k++) dst[k * NTHREADS] = r[k];
        __syncthreads();

        // issue next chunk's loads (latency hidden under conv below)
        if (ch + 1 < NCHUNK) {
            const float* src = xb + (size_t)(ch + 1) * CPC * PLANE;
            #pragma unroll
            for (int k = 0; k < KMAX; k++) r[k] = src[goff[k]];
        }

        if (ch == 0) {                // biases are in smem after first barrier
            #pragma unroll
            for (int o = 0; o < 10; o++) {
                float b = sm[BS + o0 + o];
                u64 bb = pk2(b, b);
                acc[0][o] = bb; acc[1][o] = bb; acc[2][o] = bb;
            }
        }

        #pragma unroll 2
        for (int cc = 0; cc < CPC; cc++) {
            float4 wA = *(const float4*)(wrow);
            float4 wB = *(const float4*)(wrow + 4);
            float2 wC = *(const float2*)(wrow + 8);
            wrow += 12;
            u64 W[10];
            W[0] = pk2(wA.x, wA.x); W[1] = pk2(wA.y, wA.y);
            W[2] = pk2(wA.z, wA.z); W[3] = pk2(wA.w, wA.w);
            W[4] = pk2(wB.x, wB.x); W[5] = pk2(wB.y, wB.y);
            W[6] = pk2(wB.z, wB.z); W[7] = pk2(wB.w, wB.w);
            W[8] = pk2(wC.x, wC.x); W[9] = pk2(wC.y, wC.y);

            u64 X0 = *(const u64*)xp0; xp0 += NHP;
            u64 X1 = *(const u64*)xp1; xp1 += NHP;
            u64 X2 = *(const u64*)xp2; xp2 += NHP;

            #pragma unroll
            for (int o = 0; o < 10; o++) {
                acc[0][o] = ffma2(W[o], X0, acc[0][o]);
                acc[1][o] = ffma2(W[o], X1, acc[1][o]);
                acc[2][o] = ffma2(W[o], X2, acc[2][o]);
            }
        }
    }
    #pragma unroll
    for (int rr = 0; rr < 3; rr++)
        #pragma unroll
        for (int o = 0; o < 10; o++)
            *(u64*)(sm + CO + (o0 + o) * NHP + 2 * ppc[rr]) = acc[rr][o];
    __syncthreads();

    // ---------------- phase 2a: attention MLP logits (tap-split) --------------
    {
        const int pix = tid & 255;
        const int tg  = tid >> 8;                 // 0: taps 0-4, 1: taps 5-8
        const int iy = pix >> 5, ix = pix & 31;
        const int gx = tx0 + ix, gy = ty0 + iy;
        const int hs = (iy + 1) * HW_ + ix + 1;
        const float STEP = 2.0f / 255.0f;
        const float pw00 = sm[PW], pw01 = sm[PW + 1], pw10 = sm[PW + 2], pw11 = sm[PW + 3];

        float x1r[8];
        #pragma unroll
        for (int c = 0; c < 8; c++) x1r[c] = sm[CO + c * NHP + hs];
        float t1r[10];
        #pragma unroll
        for (int c = 0; c < 10; c++) t1r[c] = sm[T1 + c];

        int kk[5], hn[5];
        float h1[5][8];
        {
            float wm8[8], wm9[8];
            #pragma unroll
            for (int o = 0; o < 8; o++) { wm8[o] = sm[WM + o * 10 + 8]; wm9[o] = sm[WM + o * 10 + 9]; }
            #pragma unroll
            for (int kt = 0; kt < 5; kt++) {
                int k = tg * 5 + kt; if (k > 8) k = 8;     // tg1 duplicates tap 8 (benign)
                kk[kt] = k;
                int dy = k / 3 - 1, dx = k - (k / 3) * 3 - 1;
                hn[kt] = hs + dy * HW_ + dx;
                float dlw = (float)(gx - reflect(gx + dx)) * STEP;
                float dlh = (float)(gy - reflect(gy + dy)) * STEP;
                float a8 = fmaxf(pw00 * dlw + pw01 * dlh + t1r[8], 0.0f);
                float a9 = fmaxf(pw10 * dlw + pw11 * dlh + t1r[9], 0.0f);
                #pragma unroll
                for (int o = 0; o < 8; o++) h1[kt][o] = wm8[o] * a8 + wm9[o] * a9;
            }
        }
        #pragma unroll
        for (int c = 0; c < 8; c++) {
            float wmc[8];
            #pragma unroll
            for (int o = 0; o < 8; o++) wmc[o] = sm[WM + o * 10 + c];
            const float t1c = t1r[c];
            const float* x2p = sm + CO + (8 + c) * NHP;
            #pragma unroll
            for (int kt = 0; kt < 5; kt++) {
                float a = fmaxf(x1r[c] - x2p[hn[kt]] + t1c, 0.0f);
                #pragma unroll
                for (int o = 0; o < 8; o++) h1[kt][o] = fmaf(wmc[o], a, h1[kt][o]);
            }
        }
        float woR[8], t2R[8];
        #pragma unroll
        for (int o = 0; o < 8; o++) { woR[o] = sm[WO + o]; t2R[o] = sm[T2 + o]; }
        const float boR = sm[BO];
        #pragma unroll
        for (int kt = 0; kt < 5; kt++) {
            float l = boR;
            #pragma unroll
            for (int o = 0; o < 8; o++)
                l = fmaf(woR[o], fmaxf(h1[kt][o] + t2R[o], 0.0f), l);
            sm[L_ + kk[kt] * 256 + pix] = l;   // tg1 kt=4 rewrites tap 8 with same value
        }
    }
    __syncthreads();

    // ---------------- phase 2b: softmax + aggregation (pixel pairs) -----------
    {
        const int pr = tid & 127;              // pixel pair index
        const int cg = tid >> 7;               // channel group (16 ch)
        const int pix0 = pr * 2;
        const int iy = pix0 >> 5, ix0 = pix0 & 31;
        const int gy = ty0 + iy, gx0 = tx0 + ix0;

        float l0[9], l1[9];
        #pragma unroll
        for (int k = 0; k < 9; k++) {
            float2 lv = *(const float2*)(sm + L_ + k * 256 + pix0);
            l0[k] = lv.x; l1[k] = lv.y;
        }
        float m0 = l0[0], m1 = l1[0];
        #pragma unroll
        for (int k = 1; k < 9; k++) { m0 = fmaxf(m0, l0[k]); m1 = fmaxf(m1, l1[k]); }
        float e0[9], e1[9], s0 = 0.0f, s1 = 0.0f;
        #pragma unroll
        for (int k = 0; k < 9; k++) {
            e0[k] = __expf(l0[k] - m0); s0 += e0[k];
            e1[k] = __expf(l1[k] - m1); s1 += e1[k];
        }
        const float i0 = 1.0f / s0, i1 = 1.0f / s1;
        u64 E[9];
        #pragma unroll
        for (int k = 0; k < 9; k++) E[k] = pk2(e0[k] * i0, e1[k] * i1);

        float* op = out + ((size_t)nb * 64 + cg * 16) * PLANE + gy * IMG + gx0;
        const float* cp0 = sm + CO + (16 + cg * 16) * NHP + iy * HW_ + ix0;
        #pragma unroll 4
        for (int c = 0; c < 16; c++) {
            const float* cp = cp0 + c * NHP;
            u64 acc2 = 0ull;
            #pragma unroll
            for (int dy = 0; dy < 3; dy++) {
                const float* rp = cp + dy * HW_;
                u64 p0 = *(const u64*)rp;
                u64 p2 = *(const u64*)(rp + 2);
                float2 f01 = up2(p0), f23 = up2(p2);
                u64 p1 = pk2(f01.y, f23.x);
                acc2 = ffma2(E[dy * 3 + 0], p0, acc2);
                acc2 = ffma2(E[dy * 3 + 1], p1, acc2);
                acc2 = ffma2(E[dy * 3 + 2], p2, acc2);
            }
            *(u64*)(op + (size_t)c * PLANE) = acc2;
        }
    }
}

extern "C" void kernel_launch(void* const* d_in, const int* in_sizes, int n_in,
                              void* d_out, int out_size)
{
    const float* x     = (const float*)d_in[0];
    const float* c1w   = (const float*)d_in[1];
    const float* c1b   = (const float*)d_in[2];
    const float* c2w   = (const float*)d_in[3];
    const float* c2b   = (const float*)d_in[4];
    const float* c3w   = (const float*)d_in[5];
    const float* c3b   = (const float*)d_in[6];
    const float* cpw   = (const float*)d_in[7];
    // d_in[8] = convp_b (cancels in position differences)
    const float* bn1g  = (const float*)d_in[9];
    const float* bn1b  = (const float*)d_in[10];
    const float* bn1m  = (const float*)d_in[11];
    const float* bn1v  = (const float*)d_in[12];
    const float* wmid  = (const float*)d_in[13];
    const float* bn2g  = (const float*)d_in[14];
    const float* bn2b  = (const float*)d_in[15];
    const float* bn2m  = (const float*)d_in[16];
    const float* bn2v  = (const float*)d_in[17];
    const float* wout  = (const float*)d_in[18];
    const float* bout  = (const float*)d_in[19];
    float* out = (float*)d_out;

    const int n = in_sizes[0] / (64 * PLANE);   // 16

    cudaFuncSetAttribute(san_fused_kernel,
                         cudaFuncAttributeMaxDynamicSharedMemorySize, SMEM_BYTES);

    dim3 grid(IMG / TILE_W, IMG / TILE_H, n);   // (8, 32, 16)
    san_fused_kernel<<<grid, NTHREADS, SMEM_BYTES>>>(
        x, c1w, c1b, c2w, c2b, c3w, c3b, cpw,
        bn1g, bn1b, bn1m, bn1v, wmid,
        bn2g, bn2b, bn2m, bn2v, wout, bout, out);
}